// round 5
// baseline (speedup 1.0000x reference)
#include <cuda_runtime.h>
#include <cuda_bf16.h>
#include <math.h>

#define NN 100000
#define NE 1600000
#define HID 64
#define DN 128

// ---------------- scratch (device globals; no allocations allowed) ----------
__device__ float g_node_proj[(size_t)NN * HID];   // 25.6 MB
__device__ float g_h_new[(size_t)NN * HID];       // 25.6 MB
__device__ float g_G[(size_t)NN * 256];           // 102.4 MB gate pre-activations
__device__ float g_Bcat[256 * 128];               // packed GRU weights
__device__ float g_bias[256];                     // packed GRU bias

// ---------------- helpers ---------------------------------------------------
__device__ __forceinline__ unsigned tf32r(float x) {
    unsigned u;
    asm("cvt.rna.tf32.f32 %0, %1;" : "=r"(u) : "f"(x));
    return u;
}
__device__ __forceinline__ float tf32f(float x) { return __uint_as_float(tf32r(x)); }

__device__ __forceinline__ void mma8(float c[4], unsigned a0, unsigned a1,
                                     unsigned a2, unsigned a3,
                                     unsigned b0, unsigned b1) {
    asm volatile(
        "mma.sync.aligned.m16n8k8.row.col.f32.tf32.tf32.f32 "
        "{%0,%1,%2,%3}, {%4,%5,%6,%7}, {%8,%9}, {%0,%1,%2,%3};"
        : "+f"(c[0]), "+f"(c[1]), "+f"(c[2]), "+f"(c[3])
        : "r"(a0), "r"(a1), "r"(a2), "r"(a3), "r"(b0), "r"(b1));
}

// smem geometry for the GEMM kernels
#define PADA 132   // A tile row stride (floats): conflict-free a-frag loads
#define PADW 72    // W (k-major) row stride: conflict-free b-frag loads
#define PADP 72    // proj/hidden staging row stride
#define SMEM_FLOATS (128 * PADA + 128 * PADW)   // 26112 floats = 104448 B

// GEMM body: C[128 x 64] = A[128 x 128] * W^T, tf32 MMA, 8 warps x m16n64.
// Expects sA (128 x PADA) and sW (k-major 128 x PADW) staged + __syncthreads done.
#define GEMM_BODY(sA, sW, acc)                                                 \
    {                                                                          \
        _Pragma("unroll")                                                      \
        for (int kk = 0; kk < 128; kk += 8) {                                  \
            unsigned a0 = __float_as_uint((sA)[r1 * PADA + kk + q4]);          \
            unsigned a1 = __float_as_uint((sA)[(r1 + 8) * PADA + kk + q4]);    \
            unsigned a2 = __float_as_uint((sA)[r1 * PADA + kk + q4 + 4]);      \
            unsigned a3 = __float_as_uint((sA)[(r1 + 8) * PADA + kk + q4 + 4]);\
            _Pragma("unroll")                                                  \
            for (int j = 0; j < 8; j++) {                                      \
                unsigned b0 = __float_as_uint((sW)[(kk + q4) * PADW + j * 8 + q]);     \
                unsigned b1 = __float_as_uint((sW)[(kk + q4 + 4) * PADW + j * 8 + q]); \
                mma8(acc[j], a0, a1, a2, a3, b0, b1);                          \
            }                                                                  \
        }                                                                      \
    }

// ---------------- K0a: zero h_new -------------------------------------------
__global__ void zero_kernel() {
    size_t i = (size_t)blockIdx.x * blockDim.x + threadIdx.x;
    if (i < (size_t)NN * 16) ((float4*)g_h_new)[i] = make_float4(0.f, 0.f, 0.f, 0.f);
}

// ---------------- K0b: pack GRU weights/bias --------------------------------
// B_cat rows: [0,64)=r-gate (W_ih_r | W_hh_r), [64,128)=z-gate,
// [128,192)=i_n (W_ih_n | 0), [192,256)=h_n (0 | W_hh_n).  K = [h_new | hidden].
__global__ void pack_kernel(const float* __restrict__ W_ih,
                            const float* __restrict__ W_hh,
                            const float* __restrict__ b_ih,
                            const float* __restrict__ b_hh) {
    int i = blockIdx.x * blockDim.x + threadIdx.x;
    if (i < 256 * 128) {
        int n = i >> 7, k = i & 127;
        int g = n >> 6, c = n & 63;
        float v = 0.f;
        if (g == 0)      v = (k < 64) ? W_ih[c * 64 + k]          : W_hh[c * 64 + (k - 64)];
        else if (g == 1) v = (k < 64) ? W_ih[(64 + c) * 64 + k]   : W_hh[(64 + c) * 64 + (k - 64)];
        else if (g == 2) { if (k < 64)  v = W_ih[(128 + c) * 64 + k]; }
        else             { if (k >= 64) v = W_hh[(128 + c) * 64 + (k - 64)]; }
        g_Bcat[i] = v;
    }
    if (i < 256) {
        int g = i >> 6, c = i & 63;
        float b;
        if (g == 0)      b = b_ih[c] + b_hh[c];
        else if (g == 1) b = b_ih[64 + c] + b_hh[64 + c];
        else if (g == 2) b = b_ih[128 + c];
        else             b = b_hh[128 + c];
        g_bias[i] = b;
    }
}

// ---------------- K1: node_proj = node_feats @ W_node^T ---------------------
__global__ __launch_bounds__(256, 2) void nodeproj_kernel(
    const float* __restrict__ node_feats, const float* __restrict__ W_node) {
    extern __shared__ float sm[];
    float* sA = sm;
    float* sW = sm + 128 * PADA;
    int tid = threadIdx.x;
    size_t n0 = (size_t)blockIdx.x * 128;

    for (int i = tid; i < 128 * 32; i += 256) {
        int r = i >> 5, c = i & 31;
        float4 v = make_float4(0.f, 0.f, 0.f, 0.f);
        if (n0 + r < NN) v = *(const float4*)(node_feats + (n0 + r) * DN + c * 4);
        v.x = tf32f(v.x); v.y = tf32f(v.y); v.z = tf32f(v.z); v.w = tf32f(v.w);
        *(float4*)&sA[r * PADA + c * 4] = v;
    }
    for (int i = tid; i < 64 * 128; i += 256) {
        int n = i >> 7, k = i & 127;
        sW[k * PADW + n] = __uint_as_float(tf32r(W_node[i]));
    }
    __syncthreads();

    int lane = tid & 31, warp = tid >> 5;
    int q = lane >> 2, q4 = lane & 3;
    int r1 = warp * 16 + q;
    float acc[8][4];
#pragma unroll
    for (int j = 0; j < 8; j++) acc[j][0] = acc[j][1] = acc[j][2] = acc[j][3] = 0.f;

    GEMM_BODY(sA, sW, acc);

#pragma unroll
    for (int half = 0; half < 2; half++) {
        size_t r = n0 + r1 + half * 8;
        if (r < NN) {
#pragma unroll
            for (int j = 0; j < 8; j++) {
                float2 o = make_float2(acc[j][half * 2], acc[j][half * 2 + 1]);
                *(float2*)&g_node_proj[r * 64 + j * 8 + 2 * q4] = o;
            }
        }
    }
}

// ---------------- K2: edge kernel (GEMM + gather + softmax + scatter) -------
__global__ __launch_bounds__(256, 2) void edge_kernel(
    const float* __restrict__ edge_feats, const float* __restrict__ W_edge,
    const int* __restrict__ src, const int* __restrict__ dst,
    const float* __restrict__ node_hidden) {
    extern __shared__ float sm[];
    float* sA = sm;                    // 128 x PADA (GEMM phase)
    float* sW = sm + 128 * PADA;       // 128 x PADW (k-major W_edge)
    float* sP = sm;                    // reuse: 128 x PADP gathered node_proj
    float* sH = sm + 128 * PADP;       // reuse: 128 x PADP gathered node_hidden
    __shared__ int s_src[128], s_dst[128];

    int tid = threadIdx.x;
    size_t e0 = (size_t)blockIdx.x * 128;
    if (tid < 128) s_src[tid] = src[e0 + tid];
    else           s_dst[tid - 128] = dst[e0 + tid - 128];

    // stage edge_feats tile, rounded to tf32
    const float4* ef = (const float4*)(edge_feats + e0 * DN);
    for (int i = tid; i < 128 * 32; i += 256) {
        int r = i >> 5, c = i & 31;
        float4 v = ef[r * 32 + c];
        v.x = tf32f(v.x); v.y = tf32f(v.y); v.z = tf32f(v.z); v.w = tf32f(v.w);
        *(float4*)&sA[r * PADA + c * 4] = v;
    }
    // stage W_edge transposed to k-major
    for (int i = tid; i < 64 * 128; i += 256) {
        int n = i >> 7, k = i & 127;
        sW[k * PADW + n] = __uint_as_float(tf32r(W_edge[i]));
    }
    __syncthreads();

    int lane = tid & 31, warp = tid >> 5;
    int q = lane >> 2, q4 = lane & 3;
    int r1 = warp * 16 + q;
    float acc[8][4];
#pragma unroll
    for (int j = 0; j < 8; j++) acc[j][0] = acc[j][1] = acc[j][2] = acc[j][3] = 0.f;

    GEMM_BODY(sA, sW, acc);
    __syncthreads();   // GEMM done reading sA/sW -> safe to reuse

    // gather node_proj[src] and node_hidden[src] rows (coalesced, L2-hot)
    for (int i = tid; i < 128 * 16; i += 256) {
        int r = i >> 4, c = i & 15;
        size_t s = (size_t)s_src[r];
        *(float4*)&sP[r * PADP + c * 4] = *(const float4*)&g_node_proj[s * 64 + c * 4];
        *(float4*)&sH[r * PADP + c * 4] = *(const float4*)(node_hidden + s * 64 + c * 4);
    }
    __syncthreads();

    // epilogue: add proj, row softmax over 64, m = hidden*alpha, scatter-add
#pragma unroll
    for (int half = 0; half < 2; half++) {
        int r = r1 + half * 8;
        int d = s_dst[r];
        float v[16];
#pragma unroll
        for (int j = 0; j < 8; j++) {
            v[2 * j]     = acc[j][half * 2]     + sP[r * PADP + j * 8 + 2 * q4];
            v[2 * j + 1] = acc[j][half * 2 + 1] + sP[r * PADP + j * 8 + 2 * q4 + 1];
        }
        float mx = v[0];
#pragma unroll
        for (int t = 1; t < 16; t++) mx = fmaxf(mx, v[t]);
        mx = fmaxf(mx, __shfl_xor_sync(0xffffffffu, mx, 1));
        mx = fmaxf(mx, __shfl_xor_sync(0xffffffffu, mx, 2));
        float s = 0.f;
#pragma unroll
        for (int t = 0; t < 16; t++) { v[t] = __expf(v[t] - mx); s += v[t]; }
        s += __shfl_xor_sync(0xffffffffu, s, 1);
        s += __shfl_xor_sync(0xffffffffu, s, 2);
        float inv = 1.f / s;
        float* hrow = g_h_new + (size_t)d * 64;
#pragma unroll
        for (int j = 0; j < 8; j++) {
            float2 m2;
            m2.x = v[2 * j]     * inv * sH[r * PADP + j * 8 + 2 * q4];
            m2.y = v[2 * j + 1] * inv * sH[r * PADP + j * 8 + 2 * q4 + 1];
#if defined(__CUDA_ARCH__) && (__CUDA_ARCH__ >= 900)
            atomicAdd((float2*)(hrow + j * 8 + 2 * q4), m2);
#else
            atomicAdd(hrow + j * 8 + 2 * q4, m2.x);
            atomicAdd(hrow + j * 8 + 2 * q4 + 1, m2.y);
#endif
        }
    }
}

// ---------------- K3a: gate GEMM  G = [h_new|hidden] @ B_cat^T --------------
__global__ __launch_bounds__(256, 2) void gates_kernel(
    const float* __restrict__ node_hidden) {
    extern __shared__ float sm[];
    float* sA = sm;
    float* sW = sm + 128 * PADA;
    int tid = threadIdx.x;
    size_t n0 = (size_t)blockIdx.x * 128;
    int nc = blockIdx.y;   // 0..3: 64-wide output chunk

    for (int i = tid; i < 128 * 32; i += 256) {
        int r = i >> 5, c = i & 31;
        float4 v = make_float4(0.f, 0.f, 0.f, 0.f);
        if (n0 + r < NN) {
            if (c < 16) v = *(const float4*)&g_h_new[(n0 + r) * 64 + c * 4];
            else        v = *(const float4*)(node_hidden + (n0 + r) * 64 + (c - 16) * 4);
        }
        v.x = tf32f(v.x); v.y = tf32f(v.y); v.z = tf32f(v.z); v.w = tf32f(v.w);
        *(float4*)&sA[r * PADA + c * 4] = v;
    }
    for (int i = tid; i < 64 * 128; i += 256) {
        int n = i >> 7, k = i & 127;
        sW[k * PADW + n] = __uint_as_float(tf32r(g_Bcat[(nc * 64 + n) * 128 + k]));
    }
    __syncthreads();

    int lane = tid & 31, warp = tid >> 5;
    int q = lane >> 2, q4 = lane & 3;
    int r1 = warp * 16 + q;
    float acc[8][4];
#pragma unroll
    for (int j = 0; j < 8; j++) acc[j][0] = acc[j][1] = acc[j][2] = acc[j][3] = 0.f;

    GEMM_BODY(sA, sW, acc);

#pragma unroll
    for (int half = 0; half < 2; half++) {
        size_t r = n0 + r1 + half * 8;
        if (r < NN) {
#pragma unroll
            for (int j = 0; j < 8; j++) {
                float2 o = make_float2(acc[j][half * 2], acc[j][half * 2 + 1]);
                *(float2*)&g_G[r * 256 + nc * 64 + j * 8 + 2 * q4] = o;
            }
        }
    }
}

// ---------------- K3b: GRU elementwise epilogue -----------------------------
__global__ void gru_kernel(const float* __restrict__ node_hidden,
                           float* __restrict__ out) {
    size_t i = (size_t)blockIdx.x * blockDim.x + threadIdx.x;
    if (i >= (size_t)NN * 64) return;
    size_t row = i >> 6;
    int c = (int)(i & 63);
    const float* Gr = g_G + row * 256;
    float pr = Gr[c]       + g_bias[c];
    float pz = Gr[64 + c]  + g_bias[64 + c];
    float pi = Gr[128 + c] + g_bias[128 + c];
    float ph = Gr[192 + c] + g_bias[192 + c];
    float r = 1.f / (1.f + __expf(-pr));
    float z = 1.f / (1.f + __expf(-pz));
    float n = tanhf(pi + r * ph);
    out[i] = (1.f - z) * n + z * node_hidden[i];
}

// ---------------- launch -----------------------------------------------------
extern "C" void kernel_launch(void* const* d_in, const int* in_sizes, int n_in,
                              void* d_out, int out_size) {
    const float* node_feats  = (const float*)d_in[0];
    const float* edge_feats  = (const float*)d_in[1];
    const float* node_hidden = (const float*)d_in[2];
    const int*   src         = (const int*)d_in[3];
    const int*   dst         = (const int*)d_in[4];
    const float* W_edge      = (const float*)d_in[5];
    const float* W_node      = (const float*)d_in[6];
    const float* W_ih        = (const float*)d_in[7];
    const float* W_hh        = (const float*)d_in[8];
    const float* b_ih        = (const float*)d_in[9];
    const float* b_hh        = (const float*)d_in[10];
    float* out = (float*)d_out;

    const int smem = SMEM_FLOATS * 4;   // 104448 bytes
    cudaFuncSetAttribute(nodeproj_kernel, cudaFuncAttributeMaxDynamicSharedMemorySize, smem);
    cudaFuncSetAttribute(edge_kernel,     cudaFuncAttributeMaxDynamicSharedMemorySize, smem);
    cudaFuncSetAttribute(gates_kernel,    cudaFuncAttributeMaxDynamicSharedMemorySize, smem);

    zero_kernel<<<(NN * 16 + 255) / 256, 256>>>();
    pack_kernel<<<128, 256>>>(W_ih, W_hh, b_ih, b_hh);
    nodeproj_kernel<<<(NN + 127) / 128, 256, smem>>>(node_feats, W_node);
    edge_kernel<<<NE / 128, 256, smem>>>(edge_feats, W_edge, src, dst, node_hidden);
    gates_kernel<<<dim3((NN + 127) / 128, 4), 256, smem>>>(node_hidden);
    gru_kernel<<<(NN * 64 + 255) / 256, 256>>>(node_hidden, out);
}

// round 9
// speedup vs baseline: 2.1683x; 2.1683x over previous
#include <cuda_runtime.h>
#include <cuda_bf16.h>
#include <math.h>

#define NN 100000
#define NE 1600000
#define HID 64
#define DN 128

// ---------------- scratch (device globals; no allocations allowed) ----------
__device__ __align__(16) float g_node_proj[(size_t)NN * HID];   // 25.6 MB
__device__ __align__(16) float g_h_new[(size_t)NN * HID];       // 25.6 MB
__device__ __align__(16) float g_G[(size_t)NN * 256];           // gate pre-activations
// fragment-packed weights: [16 ksteps][32 lanes][20 floats (16 used, 4 pad)]
__device__ __align__(16) float g_WedgeF[16 * 32 * 20];
__device__ __align__(16) float g_WnodeF[16 * 32 * 20];
__device__ __align__(16) float g_BcatF[4 * 16 * 32 * 20];
__device__ float g_bias[256];

// ---------------- helpers ---------------------------------------------------
__device__ __forceinline__ void mma8(float c[4], unsigned a0, unsigned a1,
                                     unsigned a2, unsigned a3,
                                     unsigned b0, unsigned b1) {
    asm volatile(
        "mma.sync.aligned.m16n8k8.row.col.f32.tf32.tf32.f32 "
        "{%0,%1,%2,%3}, {%4,%5,%6,%7}, {%8,%9}, {%0,%1,%2,%3};"
        : "+f"(c[0]), "+f"(c[1]), "+f"(c[2]), "+f"(c[3])
        : "r"(a0), "r"(a1), "r"(a2), "r"(a3), "r"(b0), "r"(b1));
}

__device__ __forceinline__ unsigned smaddr(const void* p) {
    return (unsigned)__cvta_generic_to_shared(p);
}
__device__ __forceinline__ void cpa16(unsigned s, const void* g) {
    asm volatile("cp.async.cg.shared.global [%0], [%1], 16;" :: "r"(s), "l"(g));
}
// zero-fills when src_sz == 0 (row guard for tail blocks)
__device__ __forceinline__ void cpa16z(unsigned s, const void* g, int src_sz) {
    asm volatile("cp.async.cg.shared.global [%0], [%1], 16, %2;"
                 :: "r"(s), "l"(g), "r"(src_sz));
}
__device__ __forceinline__ void cpa_commit() {
    asm volatile("cp.async.commit_group;");
}
template <int N>
__device__ __forceinline__ void cpa_wait() {
    asm volatile("cp.async.wait_group %0;" :: "n"(N));
}

#define PADA 132   // A tile row stride (floats): conflict-free a-frag LDS
#define PADP 72    // gather staging row stride
#define WF_FLOATS (16 * 32 * 20)                 // 10240 floats = 40960 B
#define SMEM_FLOATS (128 * PADA + WF_FLOATS)     // 27136 floats = 108544 B

// GEMM body: C[128x64] = A[128x128] * W^T. A raw fp32 in smem (MMA truncates
// to tf32), W fragment-packed: per kstep each lane reads 4 float4s (LDS.128,
// conflict-free: 80B lane slots spread across all banks).
#define GEMM_BODY(sA, sWf, acc)                                                \
    {                                                                          \
        const float* wfl = (sWf) + lane * 20;                                  \
        _Pragma("unroll")                                                      \
        for (int kk = 0; kk < 16; kk++) {                                      \
            float4 f0 = *(const float4*)(wfl + kk * 640);                      \
            float4 f1 = *(const float4*)(wfl + kk * 640 + 4);                  \
            float4 f2 = *(const float4*)(wfl + kk * 640 + 8);                  \
            float4 f3 = *(const float4*)(wfl + kk * 640 + 12);                 \
            unsigned a0 = __float_as_uint((sA)[r1 * PADA + kk * 8 + q4]);      \
            unsigned a1 = __float_as_uint((sA)[(r1 + 8) * PADA + kk * 8 + q4]);\
            unsigned a2 = __float_as_uint((sA)[r1 * PADA + kk * 8 + q4 + 4]);  \
            unsigned a3 = __float_as_uint((sA)[(r1 + 8) * PADA + kk * 8 + q4 + 4]); \
            mma8(acc[0], a0, a1, a2, a3, __float_as_uint(f0.x), __float_as_uint(f0.y)); \
            mma8(acc[1], a0, a1, a2, a3, __float_as_uint(f0.z), __float_as_uint(f0.w)); \
            mma8(acc[2], a0, a1, a2, a3, __float_as_uint(f1.x), __float_as_uint(f1.y)); \
            mma8(acc[3], a0, a1, a2, a3, __float_as_uint(f1.z), __float_as_uint(f1.w)); \
            mma8(acc[4], a0, a1, a2, a3, __float_as_uint(f2.x), __float_as_uint(f2.y)); \
            mma8(acc[5], a0, a1, a2, a3, __float_as_uint(f2.z), __float_as_uint(f2.w)); \
            mma8(acc[6], a0, a1, a2, a3, __float_as_uint(f3.x), __float_as_uint(f3.y)); \
            mma8(acc[7], a0, a1, a2, a3, __float_as_uint(f3.z), __float_as_uint(f3.w)); \
        }                                                                      \
    }

// ---------------- K0a: zero h_new -------------------------------------------
__global__ void zero_kernel() {
    size_t i = (size_t)blockIdx.x * blockDim.x + threadIdx.x;
    if (i < (size_t)NN * 16) ((float4*)g_h_new)[i] = make_float4(0.f, 0.f, 0.f, 0.f);
}

// ---------------- K0b: pack fragment-ordered weights + bias -----------------
__device__ __forceinline__ float bcat_val(const float* W_ih, const float* W_hh,
                                          int n, int k) {
    int g = n >> 6, c = n & 63;
    if (g == 0) return (k < 64) ? W_ih[c * 64 + k] : W_hh[c * 64 + (k - 64)];
    if (g == 1) return (k < 64) ? W_ih[(64 + c) * 64 + k] : W_hh[(64 + c) * 64 + (k - 64)];
    if (g == 2) return (k < 64) ? W_ih[(128 + c) * 64 + k] : 0.f;
    return (k >= 64) ? W_hh[(128 + c) * 64 + (k - 64)] : 0.f;
}

__global__ void pack_kernel(const float* __restrict__ W_edge,
                            const float* __restrict__ W_node,
                            const float* __restrict__ W_ih,
                            const float* __restrict__ W_hh,
                            const float* __restrict__ b_ih,
                            const float* __restrict__ b_hh) {
    int i = blockIdx.x * blockDim.x + threadIdx.x;
    if (i < WF_FLOATS) {
        int kk = i / 640, rem = i % 640, lane = rem / 20, t = rem % 20;
        float ve = 0.f, vn = 0.f;
        if (t < 16) {
            int q = lane >> 2, q4 = lane & 3, j = t >> 1, wh = t & 1;
            int n = j * 8 + q, k = kk * 8 + q4 + 4 * wh;
            ve = W_edge[n * 128 + k];
            vn = W_node[n * 128 + k];
        }
        g_WedgeF[i] = ve;
        g_WnodeF[i] = vn;
    }
    if (i < 4 * WF_FLOATS) {
        int nc = i / WF_FLOATS, r = i % WF_FLOATS;
        int kk = r / 640, rem = r % 640, lane = rem / 20, t = rem % 20;
        float v = 0.f;
        if (t < 16) {
            int q = lane >> 2, q4 = lane & 3, j = t >> 1, wh = t & 1;
            int n = nc * 64 + j * 8 + q, k = kk * 8 + q4 + 4 * wh;
            v = bcat_val(W_ih, W_hh, n, k);
        }
        g_BcatF[i] = v;
    }
    if (i < 256) {
        int g = i >> 6, c = i & 63;
        float b;
        if (g == 0)      b = b_ih[c] + b_hh[c];
        else if (g == 1) b = b_ih[64 + c] + b_hh[64 + c];
        else if (g == 2) b = b_ih[128 + c];
        else             b = b_hh[128 + c];
        g_bias[i] = b;
    }
}

// ---------------- K1: node_proj = node_feats @ W_node^T ---------------------
__global__ __launch_bounds__(256, 2) void nodeproj_kernel(
    const float* __restrict__ node_feats) {
    extern __shared__ float sm[];
    float* sA = sm;
    float* sWf = sm + 128 * PADA;
    int tid = threadIdx.x;
    size_t n0 = (size_t)blockIdx.x * 128;
    unsigned sA_u = smaddr(sA), sWf_u = smaddr(sWf);

    for (int i = tid; i < 4096; i += 256) {
        int r = i >> 5, c = i & 31;
        bool ok = (n0 + (size_t)r < NN);
        size_t rr = ok ? (n0 + (size_t)r) : (size_t)(NN - 1);   // in-bounds addr always
        cpa16z(sA_u + r * (PADA * 4) + c * 16,
               (const char*)(node_feats + rr * DN) + c * 16, ok ? 16 : 0);
    }
    for (int i = tid; i < 2560; i += 256)
        cpa16(sWf_u + i * 16, (const char*)g_WnodeF + (size_t)i * 16);
    cpa_commit();
    cpa_wait<0>();
    __syncthreads();

    int lane = tid & 31, warp = tid >> 5;
    int q = lane >> 2, q4 = lane & 3;
    int r1 = warp * 16 + q;
    float acc[8][4];
#pragma unroll
    for (int j = 0; j < 8; j++) acc[j][0] = acc[j][1] = acc[j][2] = acc[j][3] = 0.f;

    GEMM_BODY(sA, sWf, acc);

#pragma unroll
    for (int half = 0; half < 2; half++) {
        size_t r = n0 + r1 + half * 8;
        if (r < NN) {
#pragma unroll
            for (int j = 0; j < 8; j++) {
                float2 o = make_float2(acc[j][half * 2], acc[j][half * 2 + 1]);
                *(float2*)&g_node_proj[r * 64 + j * 8 + 2 * q4] = o;
            }
        }
    }
}

// ---------------- K2: edge kernel (GEMM + gather + softmax + scatter) -------
__global__ __launch_bounds__(256, 2) void edge_kernel(
    const float* __restrict__ edge_feats,
    const int* __restrict__ src, const int* __restrict__ dst,
    const float* __restrict__ node_hidden) {
    extern __shared__ float sm[];
    float* sA = sm;                    // 128 x PADA (GEMM phase)
    float* sWf = sm + 128 * PADA;      // fragment-packed W
    float* sP = sm;                    // overlay after MMA: gathered node_proj
    float* sH = sm + 128 * PADP;       // overlay: gathered node_hidden
    __shared__ int s_src[128], s_dst[128];

    int tid = threadIdx.x;
    size_t e0 = (size_t)blockIdx.x * 128;
    unsigned sA_u = smaddr(sA), sWf_u = smaddr(sWf);
    unsigned sP_u = smaddr(sP), sH_u = smaddr(sH);
    unsigned ssrc_u = smaddr(s_src), sdst_u = smaddr(s_dst);

    // group 0: A tile (DRAM), W frags (L2), indices — all async, overlapped
    const char* gA = (const char*)(edge_feats + e0 * DN);
    for (int i = tid; i < 4096; i += 256) {
        int r = i >> 5, c = i & 31;
        cpa16(sA_u + r * (PADA * 4) + c * 16, gA + (size_t)i * 16);
    }
    for (int i = tid; i < 2560; i += 256)
        cpa16(sWf_u + i * 16, (const char*)g_WedgeF + (size_t)i * 16);
    if (tid < 32)       cpa16(ssrc_u + tid * 16, (const char*)(src + e0) + tid * 16);
    else if (tid < 64)  cpa16(sdst_u + (tid - 32) * 16, (const char*)(dst + e0) + (tid - 32) * 16);
    cpa_commit();
    cpa_wait<0>();
    __syncthreads();

    int lane = tid & 31, warp = tid >> 5;
    int q = lane >> 2, q4 = lane & 3;
    int r1 = warp * 16 + q;
    float acc[8][4];
#pragma unroll
    for (int j = 0; j < 8; j++) acc[j][0] = acc[j][1] = acc[j][2] = acc[j][3] = 0.f;

    GEMM_BODY(sA, sWf, acc);
    __syncthreads();   // all warps done reading sA/sWf -> safe to overlay

    // gathers (L2-hot), async with full MLP, one-shot latency
    for (int i = tid; i < 2048; i += 256) {
        int r = i >> 4, c = i & 15;
        size_t s = (size_t)s_src[r];
        cpa16(sP_u + r * (PADP * 4) + c * 16, (const char*)(g_node_proj + s * 64) + c * 16);
        cpa16(sH_u + r * (PADP * 4) + c * 16, (const char*)(node_hidden + s * 64) + c * 16);
    }
    cpa_commit();
    cpa_wait<0>();
    __syncthreads();

    // epilogue: add proj, row softmax over 64, m = hidden*alpha, scatter-add
#pragma unroll
    for (int half = 0; half < 2; half++) {
        int r = r1 + half * 8;
        int d = s_dst[r];
        float v[16];
#pragma unroll
        for (int j = 0; j < 8; j++) {
            v[2 * j]     = acc[j][half * 2]     + sP[r * PADP + j * 8 + 2 * q4];
            v[2 * j + 1] = acc[j][half * 2 + 1] + sP[r * PADP + j * 8 + 2 * q4 + 1];
        }
        float mx = v[0];
#pragma unroll
        for (int t = 1; t < 16; t++) mx = fmaxf(mx, v[t]);
        mx = fmaxf(mx, __shfl_xor_sync(0xffffffffu, mx, 1));
        mx = fmaxf(mx, __shfl_xor_sync(0xffffffffu, mx, 2));
        float s = 0.f;
#pragma unroll
        for (int t = 0; t < 16; t++) { v[t] = __expf(v[t] - mx); s += v[t]; }
        s += __shfl_xor_sync(0xffffffffu, s, 1);
        s += __shfl_xor_sync(0xffffffffu, s, 2);
        float inv = 1.f / s;
        float* hrow = g_h_new + (size_t)d * 64;
#pragma unroll
        for (int j = 0; j < 8; j++) {
            float2 m2;
            m2.x = v[2 * j]     * inv * sH[r * PADP + j * 8 + 2 * q4];
            m2.y = v[2 * j + 1] * inv * sH[r * PADP + j * 8 + 2 * q4 + 1];
            atomicAdd((float2*)(hrow + j * 8 + 2 * q4), m2);
        }
    }
}

// ---------------- K3a: gate GEMM  G = [h_new|hidden] @ B_cat^T --------------
__global__ __launch_bounds__(256, 2) void gates_kernel(
    const float* __restrict__ node_hidden) {
    extern __shared__ float sm[];
    float* sA = sm;
    float* sWf = sm + 128 * PADA;
    int tid = threadIdx.x;
    size_t n0 = (size_t)blockIdx.x * 128;
    int nc = blockIdx.y;   // 0..3: 64-wide output chunk
    unsigned sA_u = smaddr(sA), sWf_u = smaddr(sWf);

    for (int i = tid; i < 4096; i += 256) {
        int r = i >> 5, c = i & 31;
        bool ok = (n0 + (size_t)r < NN);
        size_t rr = ok ? (n0 + (size_t)r) : (size_t)(NN - 1);   // in-bounds addr always
        const char* p = (c < 16)
            ? (const char*)(g_h_new + rr * 64) + c * 16
            : (const char*)(node_hidden + rr * 64) + (c - 16) * 16;
        cpa16z(sA_u + r * (PADA * 4) + c * 16, p, ok ? 16 : 0);
    }
    const char* gW = (const char*)(g_BcatF + (size_t)nc * WF_FLOATS);
    for (int i = tid; i < 2560; i += 256)
        cpa16(sWf_u + i * 16, gW + (size_t)i * 16);
    cpa_commit();
    cpa_wait<0>();
    __syncthreads();

    int lane = tid & 31, warp = tid >> 5;
    int q = lane >> 2, q4 = lane & 3;
    int r1 = warp * 16 + q;
    float acc[8][4];
#pragma unroll
    for (int j = 0; j < 8; j++) acc[j][0] = acc[j][1] = acc[j][2] = acc[j][3] = 0.f;

    GEMM_BODY(sA, sWf, acc);

#pragma unroll
    for (int half = 0; half < 2; half++) {
        size_t r = n0 + r1 + half * 8;
        if (r < NN) {
#pragma unroll
            for (int j = 0; j < 8; j++) {
                float2 o = make_float2(acc[j][half * 2], acc[j][half * 2 + 1]);
                *(float2*)&g_G[r * 256 + nc * 64 + j * 8 + 2 * q4] = o;
            }
        }
    }
}

// ---------------- K3b: GRU elementwise epilogue -----------------------------
__global__ void gru_kernel(const float* __restrict__ node_hidden,
                           float* __restrict__ out) {
    size_t i = (size_t)blockIdx.x * blockDim.x + threadIdx.x;
    if (i >= (size_t)NN * 64) return;
    size_t row = i >> 6;
    int c = (int)(i & 63);
    const float* Gr = g_G + row * 256;
    float pr = Gr[c]       + g_bias[c];
    float pz = Gr[64 + c]  + g_bias[64 + c];
    float pi = Gr[128 + c] + g_bias[128 + c];
    float ph = Gr[192 + c] + g_bias[192 + c];
    float r = 1.f / (1.f + __expf(-pr));
    float z = 1.f / (1.f + __expf(-pz));
    float n = tanhf(pi + r * ph);
    out[i] = (1.f - z) * n + z * node_hidden[i];
}

// ---------------- launch -----------------------------------------------------
extern "C" void kernel_launch(void* const* d_in, const int* in_sizes, int n_in,
                              void* d_out, int out_size) {
    const float* node_feats  = (const float*)d_in[0];
    const float* edge_feats  = (const float*)d_in[1];
    const float* node_hidden = (const float*)d_in[2];
    const int*   src         = (const int*)d_in[3];
    const int*   dst         = (const int*)d_in[4];
    const float* W_edge      = (const float*)d_in[5];
    const float* W_node      = (const float*)d_in[6];
    const float* W_ih        = (const float*)d_in[7];
    const float* W_hh        = (const float*)d_in[8];
    const float* b_ih        = (const float*)d_in[9];
    const float* b_hh        = (const float*)d_in[10];
    float* out = (float*)d_out;

    const int smem = SMEM_FLOATS * 4;   // 108544 bytes
    cudaFuncSetAttribute(nodeproj_kernel, cudaFuncAttributeMaxDynamicSharedMemorySize, smem);
    cudaFuncSetAttribute(edge_kernel,     cudaFuncAttributeMaxDynamicSharedMemorySize, smem);
    cudaFuncSetAttribute(gates_kernel,    cudaFuncAttributeMaxDynamicSharedMemorySize, smem);

    zero_kernel<<<(NN * 16 + 255) / 256, 256>>>();
    pack_kernel<<<(4 * WF_FLOATS + 255) / 256, 256>>>(W_edge, W_node, W_ih, W_hh, b_ih, b_hh);
    nodeproj_kernel<<<(NN + 127) / 128, 256, smem>>>(node_feats);
    edge_kernel<<<NE / 128, 256, smem>>>(edge_feats, src, dst, node_hidden);
    gates_kernel<<<dim3((NN + 127) / 128, 4), 256, smem>>>(node_hidden);
    gru_kernel<<<(NN * 64 + 255) / 256, 256>>>(node_hidden, out);
}

// round 13
// speedup vs baseline: 2.2416x; 1.0338x over previous
#include <cuda_runtime.h>
#include <cuda_bf16.h>
#include <math.h>

#define NN 100000
#define NE 1600000
#define HID 64
#define DN 128

// ---------------- scratch (device globals; no allocations allowed) ----------
__device__ __align__(16) float g_node_proj[(size_t)NN * HID];   // 25.6 MB
__device__ __align__(16) float g_h_new[(size_t)NN * HID];       // 25.6 MB
// fragment-packed weights: [16 ksteps][32 lanes][20 floats (16 used, 4 pad)]
__device__ __align__(16) float g_WedgeF[16 * 32 * 20];
__device__ __align__(16) float g_WnodeF[16 * 32 * 20];
__device__ __align__(16) float g_BcatF[4 * 16 * 32 * 20];
__device__ float g_bias[256];

// ---------------- helpers ---------------------------------------------------
__device__ __forceinline__ void mma8(float c[4], unsigned a0, unsigned a1,
                                     unsigned a2, unsigned a3,
                                     unsigned b0, unsigned b1) {
    asm volatile(
        "mma.sync.aligned.m16n8k8.row.col.f32.tf32.tf32.f32 "
        "{%0,%1,%2,%3}, {%4,%5,%6,%7}, {%8,%9}, {%0,%1,%2,%3};"
        : "+f"(c[0]), "+f"(c[1]), "+f"(c[2]), "+f"(c[3])
        : "r"(a0), "r"(a1), "r"(a2), "r"(a3), "r"(b0), "r"(b1));
}

__device__ __forceinline__ unsigned smaddr(const void* p) {
    return (unsigned)__cvta_generic_to_shared(p);
}
__device__ __forceinline__ void cpa16(unsigned s, const void* g) {
    asm volatile("cp.async.cg.shared.global [%0], [%1], 16;" :: "r"(s), "l"(g));
}
// evict-first variant for read-once streams (protects L2 working set)
__device__ __forceinline__ void cpa16_ef(unsigned s, const void* g) {
    asm volatile(
        "{\n\t.reg .b64 pol;\n\t"
        "createpolicy.fractional.L2::evict_first.b64 pol, 1.0;\n\t"
        "cp.async.cg.shared.global.L2::cache_hint [%0], [%1], 16, pol;\n\t}"
        :: "r"(s), "l"(g));
}
// zero-fills when src_sz == 0 (row guard for tail blocks)
__device__ __forceinline__ void cpa16z(unsigned s, const void* g, int src_sz) {
    asm volatile("cp.async.cg.shared.global [%0], [%1], 16, %2;"
                 :: "r"(s), "l"(g), "r"(src_sz));
}
__device__ __forceinline__ void cpa16z_ef(unsigned s, const void* g, int src_sz) {
    asm volatile(
        "{\n\t.reg .b64 pol;\n\t"
        "createpolicy.fractional.L2::evict_first.b64 pol, 1.0;\n\t"
        "cp.async.cg.shared.global.L2::cache_hint [%0], [%1], 16, %2, pol;\n\t}"
        :: "r"(s), "l"(g), "r"(src_sz));
}
__device__ __forceinline__ void cpa_commit() {
    asm volatile("cp.async.commit_group;");
}
template <int N>
__device__ __forceinline__ void cpa_wait() {
    asm volatile("cp.async.wait_group %0;" :: "n"(N));
}
__device__ __forceinline__ void prefetchL2(const void* g) {
    asm volatile("prefetch.global.L2 [%0];" :: "l"(g));
}

#define PADA 132   // A tile row stride (floats): conflict-free a-frag LDS
#define PADP 72    // gather staging row stride
#define WF_FLOATS (16 * 32 * 20)                 // 10240 floats = 40960 B
#define SMEM_FLOATS (128 * PADA + WF_FLOATS)     // 27136 floats = 108544 B
#define WAVE_TILES 296                            // 148 SMs x occ 2 (prefetch distance)

// GEMM body: C[128x64] = A[128x128] * W^T. A raw fp32 in smem (MMA truncates
// to tf32), W fragment-packed: per kstep each lane reads 4 float4s (LDS.128,
// conflict-free: 80B lane slots spread across all banks).
#define GEMM_BODY(sA, sWf, acc)                                                \
    {                                                                          \
        const float* wfl = (sWf) + lane * 20;                                  \
        _Pragma("unroll")                                                      \
        for (int kk = 0; kk < 16; kk++) {                                      \
            float4 f0 = *(const float4*)(wfl + kk * 640);                      \
            float4 f1 = *(const float4*)(wfl + kk * 640 + 4);                  \
            float4 f2 = *(const float4*)(wfl + kk * 640 + 8);                  \
            float4 f3 = *(const float4*)(wfl + kk * 640 + 12);                 \
            unsigned a0 = __float_as_uint((sA)[r1 * PADA + kk * 8 + q4]);      \
            unsigned a1 = __float_as_uint((sA)[(r1 + 8) * PADA + kk * 8 + q4]);\
            unsigned a2 = __float_as_uint((sA)[r1 * PADA + kk * 8 + q4 + 4]);  \
            unsigned a3 = __float_as_uint((sA)[(r1 + 8) * PADA + kk * 8 + q4 + 4]); \
            mma8(acc[0], a0, a1, a2, a3, __float_as_uint(f0.x), __float_as_uint(f0.y)); \
            mma8(acc[1], a0, a1, a2, a3, __float_as_uint(f0.z), __float_as_uint(f0.w)); \
            mma8(acc[2], a0, a1, a2, a3, __float_as_uint(f1.x), __float_as_uint(f1.y)); \
            mma8(acc[3], a0, a1, a2, a3, __float_as_uint(f1.z), __float_as_uint(f1.w)); \
            mma8(acc[4], a0, a1, a2, a3, __float_as_uint(f2.x), __float_as_uint(f2.y)); \
            mma8(acc[5], a0, a1, a2, a3, __float_as_uint(f2.z), __float_as_uint(f2.w)); \
            mma8(acc[6], a0, a1, a2, a3, __float_as_uint(f3.x), __float_as_uint(f3.y)); \
            mma8(acc[7], a0, a1, a2, a3, __float_as_uint(f3.z), __float_as_uint(f3.w)); \
        }                                                                      \
    }

// ---------------- K0a: zero h_new -------------------------------------------
__global__ void zero_kernel() {
    size_t i = (size_t)blockIdx.x * blockDim.x + threadIdx.x;
    if (i < (size_t)NN * 16) ((float4*)g_h_new)[i] = make_float4(0.f, 0.f, 0.f, 0.f);
}

// ---------------- K0b: pack fragment-ordered weights + bias -----------------
__device__ __forceinline__ float bcat_val(const float* W_ih, const float* W_hh,
                                          int n, int k) {
    int g = n >> 6, c = n & 63;
    if (g == 0) return (k < 64) ? W_ih[c * 64 + k] : W_hh[c * 64 + (k - 64)];
    if (g == 1) return (k < 64) ? W_ih[(64 + c) * 64 + k] : W_hh[(64 + c) * 64 + (k - 64)];
    if (g == 2) return (k < 64) ? W_ih[(128 + c) * 64 + k] : 0.f;
    return (k >= 64) ? W_hh[(128 + c) * 64 + (k - 64)] : 0.f;
}

__global__ void pack_kernel(const float* __restrict__ W_edge,
                            const float* __restrict__ W_node,
                            const float* __restrict__ W_ih,
                            const float* __restrict__ W_hh,
                            const float* __restrict__ b_ih,
                            const float* __restrict__ b_hh) {
    int i = blockIdx.x * blockDim.x + threadIdx.x;
    if (i < WF_FLOATS) {
        int kk = i / 640, rem = i % 640, lane = rem / 20, t = rem % 20;
        float ve = 0.f, vn = 0.f;
        if (t < 16) {
            int q = lane >> 2, q4 = lane & 3, j = t >> 1, wh = t & 1;
            int n = j * 8 + q, k = kk * 8 + q4 + 4 * wh;
            ve = W_edge[n * 128 + k];
            vn = W_node[n * 128 + k];
        }
        g_WedgeF[i] = ve;
        g_WnodeF[i] = vn;
    }
    if (i < 4 * WF_FLOATS) {
        int nc = i / WF_FLOATS, r = i % WF_FLOATS;
        int kk = r / 640, rem = r % 640, lane = rem / 20, t = rem % 20;
        float v = 0.f;
        if (t < 16) {
            int q = lane >> 2, q4 = lane & 3, j = t >> 1, wh = t & 1;
            int n = nc * 64 + j * 8 + q, k = kk * 8 + q4 + 4 * wh;
            v = bcat_val(W_ih, W_hh, n, k);
        }
        g_BcatF[i] = v;
    }
    if (i < 256) {
        int g = i >> 6, c = i & 63;
        float b;
        if (g == 0)      b = b_ih[c] + b_hh[c];
        else if (g == 1) b = b_ih[64 + c] + b_hh[64 + c];
        else if (g == 2) b = b_ih[128 + c];
        else             b = b_hh[128 + c];
        g_bias[i] = b;
    }
}

// ---------------- K1: node_proj = node_feats @ W_node^T ---------------------
__global__ __launch_bounds__(256, 2) void nodeproj_kernel(
    const float* __restrict__ node_feats) {
    extern __shared__ float sm[];
    float* sA = sm;
    float* sWf = sm + 128 * PADA;
    int tid = threadIdx.x;
    size_t n0 = (size_t)blockIdx.x * 128;
    unsigned sA_u = smaddr(sA), sWf_u = smaddr(sWf);

    for (int i = tid; i < 4096; i += 256) {
        int r = i >> 5, c = i & 31;
        bool ok = (n0 + (size_t)r < NN);
        size_t rr = ok ? (n0 + (size_t)r) : (size_t)(NN - 1);   // in-bounds addr always
        cpa16z_ef(sA_u + r * (PADA * 4) + c * 16,
                  (const char*)(node_feats + rr * DN) + c * 16, ok ? 16 : 0);
    }
    for (int i = tid; i < 2560; i += 256)
        cpa16(sWf_u + i * 16, (const char*)g_WnodeF + (size_t)i * 16);
    cpa_commit();
    cpa_wait<0>();
    __syncthreads();

    int lane = tid & 31, warp = tid >> 5;
    int q = lane >> 2, q4 = lane & 3;
    int r1 = warp * 16 + q;
    float acc[8][4];
#pragma unroll
    for (int j = 0; j < 8; j++) acc[j][0] = acc[j][1] = acc[j][2] = acc[j][3] = 0.f;

    GEMM_BODY(sA, sWf, acc);

#pragma unroll
    for (int half = 0; half < 2; half++) {
        size_t r = n0 + r1 + half * 8;
        if (r < NN) {
#pragma unroll
            for (int j = 0; j < 8; j++) {
                float2 o = make_float2(acc[j][half * 2], acc[j][half * 2 + 1]);
                *(float2*)&g_node_proj[r * 64 + j * 8 + 2 * q4] = o;
            }
        }
    }
}

// ---------------- K2: edge kernel (GEMM + gather + softmax + scatter) -------
__global__ __launch_bounds__(256, 2) void edge_kernel(
    const float* __restrict__ edge_feats,
    const int* __restrict__ src, const int* __restrict__ dst,
    const float* __restrict__ node_hidden) {
    extern __shared__ float sm[];
    float* sA = sm;                    // 128 x PADA (GEMM phase)
    float* sWf = sm + 128 * PADA;      // fragment-packed W
    float* sP = sm;                    // overlay after MMA: gathered node_proj
    float* sH = sm + 128 * PADP;       // overlay: gathered node_hidden
    __shared__ int s_src[128], s_dst[128];

    int tid = threadIdx.x;
    size_t e0 = (size_t)blockIdx.x * 128;
    unsigned sA_u = smaddr(sA), sWf_u = smaddr(sWf);
    unsigned sP_u = smaddr(sP), sH_u = smaddr(sH);
    unsigned ssrc_u = smaddr(s_src), sdst_u = smaddr(s_dst);

    // group 0: A tile (DRAM, evict-first), W frags (L2), indices — all async
    const char* gA = (const char*)(edge_feats + e0 * DN);
    for (int i = tid; i < 4096; i += 256) {
        int r = i >> 5, c = i & 31;
        cpa16_ef(sA_u + r * (PADA * 4) + c * 16, gA + (size_t)i * 16);
    }
    for (int i = tid; i < 2560; i += 256)
        cpa16(sWf_u + i * 16, (const char*)g_WedgeF + (size_t)i * 16);
    if (tid < 32)       cpa16(ssrc_u + tid * 16, (const char*)(src + e0) + tid * 16);
    else if (tid < 64)  cpa16(sdst_u + (tid - 32) * 16, (const char*)(dst + e0) + (tid - 32) * 16);
    cpa_commit();

    // L2 prefetch of the A tile one wave ahead (hides DRAM latency at tile start)
    {
        size_t ep = e0 + (size_t)WAVE_TILES * 128;
        if (ep < NE) {
            const char* gp = (const char*)(edge_feats + ep * DN);
#pragma unroll
            for (int u = 0; u < 2; u++)
                prefetchL2(gp + ((size_t)tid + 256 * u) * 128);
        }
    }

    cpa_wait<0>();
    __syncthreads();

    int lane = tid & 31, warp = tid >> 5;
    int q = lane >> 2, q4 = lane & 3;
    int r1 = warp * 16 + q;
    float acc[8][4];
#pragma unroll
    for (int j = 0; j < 8; j++) acc[j][0] = acc[j][1] = acc[j][2] = acc[j][3] = 0.f;

    GEMM_BODY(sA, sWf, acc);
    __syncthreads();   // all warps done reading sA/sWf -> safe to overlay

    // gathers (L2-hot), async with full MLP, one-shot latency
    for (int i = tid; i < 2048; i += 256) {
        int r = i >> 4, c = i & 15;
        size_t s = (size_t)s_src[r];
        cpa16(sP_u + r * (PADP * 4) + c * 16, (const char*)(g_node_proj + s * 64) + c * 16);
        cpa16(sH_u + r * (PADP * 4) + c * 16, (const char*)(node_hidden + s * 64) + c * 16);
    }
    cpa_commit();
    cpa_wait<0>();
    __syncthreads();

    // epilogue: add proj, row softmax over 64, m = hidden*alpha, scatter-add
#pragma unroll
    for (int half = 0; half < 2; half++) {
        int r = r1 + half * 8;
        int d = s_dst[r];
        float v[16];
#pragma unroll
        for (int j = 0; j < 8; j++) {
            v[2 * j]     = acc[j][half * 2]     + sP[r * PADP + j * 8 + 2 * q4];
            v[2 * j + 1] = acc[j][half * 2 + 1] + sP[r * PADP + j * 8 + 2 * q4 + 1];
        }
        float mx = v[0];
#pragma unroll
        for (int t = 1; t < 16; t++) mx = fmaxf(mx, v[t]);
        mx = fmaxf(mx, __shfl_xor_sync(0xffffffffu, mx, 1));
        mx = fmaxf(mx, __shfl_xor_sync(0xffffffffu, mx, 2));
        float s = 0.f;
#pragma unroll
        for (int t = 0; t < 16; t++) { v[t] = __expf(v[t] - mx); s += v[t]; }
        s += __shfl_xor_sync(0xffffffffu, s, 1);
        s += __shfl_xor_sync(0xffffffffu, s, 2);
        float inv = 1.f / s;
        float* hrow = g_h_new + (size_t)d * 64;
#pragma unroll
        for (int j = 0; j < 8; j++) {
            float2 m2;
            m2.x = v[2 * j]     * inv * sH[r * PADP + j * 8 + 2 * q4];
            m2.y = v[2 * j + 1] * inv * sH[r * PADP + j * 8 + 2 * q4 + 1];
            atomicAdd((float2*)(hrow + j * 8 + 2 * q4), m2);
        }
    }
}

// ---------------- K3: fused gates GEMM + GRU epilogue -----------------------
// One block stages A=[h_new|hidden] for 128 nodes once, runs 4 chunk GEMMs
// (r, z, i_n, h_n) reloading only the 40KB W-chunk between them (overlapped
// with acc post-processing), keeps r/z/pi in registers, writes d_out directly.
__global__ __launch_bounds__(256) void gatesgru_kernel(
    const float* __restrict__ node_hidden, float* __restrict__ out) {
    extern __shared__ float sm[];
    float* sA = sm;
    float* sWf = sm + 128 * PADA;
    __shared__ float sbias[256];
    int tid = threadIdx.x;
    size_t n0 = (size_t)blockIdx.x * 128;
    unsigned sA_u = smaddr(sA), sWf_u = smaddr(sWf);

    sbias[tid] = g_bias[tid];

    for (int i = tid; i < 4096; i += 256) {
        int r = i >> 5, c = i & 31;
        bool ok = (n0 + (size_t)r < NN);
        size_t rr = ok ? (n0 + (size_t)r) : (size_t)(NN - 1);
        const char* p = (c < 16)
            ? (const char*)(g_h_new + rr * 64) + c * 16
            : (const char*)(node_hidden + rr * 64) + (c - 16) * 16;
        cpa16z(sA_u + r * (PADA * 4) + c * 16, p, ok ? 16 : 0);
    }
    for (int i = tid; i < 2560; i += 256)
        cpa16(sWf_u + i * 16, (const char*)g_BcatF + (size_t)i * 16);
    cpa_commit();
    cpa_wait<0>();
    __syncthreads();

    int lane = tid & 31, warp = tid >> 5;
    int q = lane >> 2, q4 = lane & 3;
    int r1 = warp * 16 + q;

    float rg[8][4], zg[8][4], pi[8][4];

#define GATE_STAGE(accv, NCNEXT)                                               \
    float accv[8][4];                                                          \
    _Pragma("unroll")                                                          \
    for (int j = 0; j < 8; j++)                                                \
        accv[j][0] = accv[j][1] = accv[j][2] = accv[j][3] = 0.f;               \
    GEMM_BODY(sA, sWf, accv);                                                  \
    __syncthreads();                                                           \
    {                                                                          \
        const char* gW = (const char*)(g_BcatF + (size_t)(NCNEXT)*WF_FLOATS);  \
        for (int i = tid; i < 2560; i += 256)                                  \
            cpa16(sWf_u + i * 16, gW + (size_t)i * 16);                        \
        cpa_commit();                                                          \
    }

    // chunk 0: r gate
    {
        GATE_STAGE(acc0, 1)
#pragma unroll
        for (int j = 0; j < 8; j++)
#pragma unroll
            for (int k = 0; k < 4; k++) {
                int col = j * 8 + 2 * q4 + (k & 1);
                rg[j][k] = 1.f / (1.f + __expf(-(acc0[j][k] + sbias[col])));
            }
        cpa_wait<0>();
        __syncthreads();
    }
    // chunk 1: z gate
    {
        GATE_STAGE(acc1, 2)
#pragma unroll
        for (int j = 0; j < 8; j++)
#pragma unroll
            for (int k = 0; k < 4; k++) {
                int col = j * 8 + 2 * q4 + (k & 1);
                zg[j][k] = 1.f / (1.f + __expf(-(acc1[j][k] + sbias[64 + col])));
            }
        cpa_wait<0>();
        __syncthreads();
    }
    // chunk 2: i_n pre-activation
    {
        GATE_STAGE(acc2, 3)
#pragma unroll
        for (int j = 0; j < 8; j++)
#pragma unroll
            for (int k = 0; k < 4; k++) {
                int col = j * 8 + 2 * q4 + (k & 1);
                pi[j][k] = acc2[j][k] + sbias[128 + col];
            }
        cpa_wait<0>();
        __syncthreads();
    }
    // chunk 3: h_n + final GRU combine
    {
        float acc3[8][4];
#pragma unroll
        for (int j = 0; j < 8; j++)
            acc3[j][0] = acc3[j][1] = acc3[j][2] = acc3[j][3] = 0.f;
        GEMM_BODY(sA, sWf, acc3);

#pragma unroll
        for (int half = 0; half < 2; half++) {
            int row = r1 + half * 8;
            size_t grow = n0 + (size_t)row;
            if (grow < NN) {
#pragma unroll
                for (int j = 0; j < 8; j++) {
                    int col = j * 8 + 2 * q4;
                    float2 o;
#pragma unroll
                    for (int s = 0; s < 2; s++) {
                        int k = half * 2 + s;
                        float ph = acc3[j][k] + sbias[192 + col + s];
                        float n = tanhf(pi[j][k] + rg[j][k] * ph);
                        float h = sA[row * PADA + 64 + col + s];
                        float v = (1.f - zg[j][k]) * n + zg[j][k] * h;
                        if (s == 0) o.x = v; else o.y = v;
                    }
                    *(float2*)&out[grow * 64 + col] = o;
                }
            }
        }
    }
#undef GATE_STAGE
}

// ---------------- launch -----------------------------------------------------
extern "C" void kernel_launch(void* const* d_in, const int* in_sizes, int n_in,
                              void* d_out, int out_size) {
    const float* node_feats  = (const float*)d_in[0];
    const float* edge_feats  = (const float*)d_in[1];
    const float* node_hidden = (const float*)d_in[2];
    const int*   src         = (const int*)d_in[3];
    const int*   dst         = (const int*)d_in[4];
    const float* W_edge      = (const float*)d_in[5];
    const float* W_node      = (const float*)d_in[6];
    const float* W_ih        = (const float*)d_in[7];
    const float* W_hh        = (const float*)d_in[8];
    const float* b_ih        = (const float*)d_in[9];
    const float* b_hh        = (const float*)d_in[10];
    float* out = (float*)d_out;

    const int smem = SMEM_FLOATS * 4;   // 108544 bytes
    cudaFuncSetAttribute(nodeproj_kernel, cudaFuncAttributeMaxDynamicSharedMemorySize, smem);
    cudaFuncSetAttribute(edge_kernel,     cudaFuncAttributeMaxDynamicSharedMemorySize, smem);
    cudaFuncSetAttribute(gatesgru_kernel, cudaFuncAttributeMaxDynamicSharedMemorySize, smem);

    zero_kernel<<<(NN * 16 + 255) / 256, 256>>>();
    pack_kernel<<<(4 * WF_FLOATS + 255) / 256, 256>>>(W_edge, W_node, W_ih, W_hh, b_ih, b_hh);
    nodeproj_kernel<<<(NN + 127) / 128, 256, smem>>>(node_feats);
    edge_kernel<<<NE / 128, 256, smem>>>(edge_feats, src, dst, node_hidden);
    gatesgru_kernel<<<(NN + 127) / 128, 256, smem>>>(node_hidden, out);
}